// round 12
// baseline (speedup 1.0000x reference)
#include <cuda_runtime.h>
#include <cstdint>
#include <cstddef>

// Problem constants
#define B_TOT  131072
#define T_DIM  5
#define V_DIM  60
#define TV     300
#define KB     32                 // b-rows per k-tile
#define NC     296                // CTAs in kernel 1
#define NTILES (B_TOT / KB)       // 4096
#define RDW    140                // sRd row stride in floats (swizzle-padded)

// Per-CTA partial M slabs, TRANSPOSED: part[c][j*60 + v] = M_c[v][j]
__device__ float g_part[NC * 3600];
// Stage-a output: g_red[(j*60+v)*8 + s]
__device__ float g_red[3600 * 8];

// Packed f32x2 FMA (sm_100+); scalar fallback otherwise. Same numerics (.rn).
__device__ __forceinline__ unsigned long long fma2(unsigned long long a,
                                                   unsigned long long b,
                                                   unsigned long long c) {
#if defined(__CUDA_ARCH__) && (__CUDA_ARCH__ >= 1000)
    unsigned long long d;
    asm("fma.rn.f32x2 %0, %1, %2, %3;" : "=l"(d) : "l"(a), "l"(b), "l"(c));
    return d;
#else
    float2 fa = *reinterpret_cast<float2*>(&a);
    float2 fb = *reinterpret_cast<float2*>(&b);
    float2 fc = *reinterpret_cast<float2*>(&c);
    float2 fd;
    fd.x = fmaf(fa.x, fb.x, fc.x);
    fd.y = fmaf(fa.y, fb.y, fc.y);
    return *reinterpret_cast<unsigned long long*>(&fd);
#endif
}

// ============================================================================
// Kernel 1: thread tile 8v x 4j, f32x2 pairs along v.
//   sA [k][v]       plain a, 64-float rows  -> a LDS.128 broadcasts (natural
//                                              {a2v,a2v+1} pairs, zero MOVs)
//   sRd[k][dup(j)]  r pre-duplicated {r,r}, swizzled rows (140 floats):
//                   word off = 8*tx + 4*(tx>>2)  -> both LDS.128 conflict-free
// Phase B per kk: 4 LDS.128 + 16 FFMA2, no MOVs. 3 CTAs/SM (24 warps).
// Dynamic smem: sA[2][2048] + sRd[2][32*140] = 52224 B (x3 = 157 KB).
// ============================================================================
__global__ __launch_bounds__(256, 3)
void k1_gram(const float* __restrict__ x,
             const float* __restrict__ W1,
             const float* __restrict__ W3) {
    extern __shared__ float smem[];
    float* sA[2]  = { smem, smem + KB * 64 };
    float* sRd[2] = { smem + 2 * KB * 64, smem + 2 * KB * 64 + KB * RDW };

    const int tid = threadIdx.x;

    float w1[T_DIM], w3[T_DIM];
#pragma unroll
    for (int t = 0; t < T_DIM; t++) { w1[t] = W1[t]; w3[t] = W3[t]; }

    // Phase-B mapping: 2 k-groups x (8 ty x 16 tx); tile 8v x 4j per thread
    const int grp = tid >> 7;        // 0..1 : handles k = grp + 2*kk
    const int gt  = tid & 127;
    const int ty  = gt >> 4;         // 0..7 : v = ty*8 + 2*vp + {0,1}
    const int tx  = gt & 15;         // 0..15: j = tx*4 + jj
    const int rdOff = tx * 8 + (tx >> 2) * 4;   // swizzled dup-r base (words)

    // Phase-A mapping: 16 b-rows x 16 v-lanes (lane 15 = zero pad), 2 passes
    const int rowA  = tid >> 4;      // 0..15
    const int laneA = tid & 15;      // 0..15
    const int wrOff = laneA * 8 + (laneA >> 2) * 4;

    unsigned long long acc[4][4];    // [vp][jj] -> 32 registers
#pragma unroll
    for (int vp = 0; vp < 4; vp++)
#pragma unroll
        for (int jj = 0; jj < 4; jj++) acc[vp][jj] = 0ull;

    auto phaseA = [&](int tile, int buf) {
#pragma unroll
        for (int p = 0; p < 2; p++) {
            const int k = rowA + 16 * p;             // 0..31
            float4 a4 = make_float4(0.f, 0.f, 0.f, 0.f);
            float4 r4 = make_float4(0.f, 0.f, 0.f, 0.f);
            if (laneA < 15) {
                const float* xb = x + (size_t)(tile * KB + k) * TV + laneA * 4;
#pragma unroll
                for (int t = 0; t < T_DIM; t++) {
                    float4 xv = *(const float4*)(xb + t * V_DIM);
                    a4.x = fmaf(xv.x, w1[t], a4.x); r4.x = fmaf(xv.x, w3[t], r4.x);
                    a4.y = fmaf(xv.y, w1[t], a4.y); r4.y = fmaf(xv.y, w3[t], r4.y);
                    a4.z = fmaf(xv.z, w1[t], a4.z); r4.z = fmaf(xv.z, w3[t], r4.z);
                    a4.w = fmaf(xv.w, w1[t], a4.w); r4.w = fmaf(xv.w, w3[t], r4.w);
                }
            }
            *(float4*)&sA[buf][k * 64 + laneA * 4] = a4;
            float* pr = &sRd[buf][k * RDW + wrOff];
            *(float4*)(pr)     = make_float4(r4.x, r4.x, r4.y, r4.y);
            *(float4*)(pr + 4) = make_float4(r4.z, r4.z, r4.w, r4.w);
        }
    };

    // Prologue
    phaseA(blockIdx.x, 0);
    __syncthreads();

    int buf = 0;
    for (int tile = blockIdx.x; tile < NTILES; tile += NC) {
        // ---------- Phase B on buf: 16 kk x (4 LDS.128 + 16 fma2) ----------
#pragma unroll
        for (int kk = 0; kk < KB / 2; kk++) {
            const int k = grp + kk * 2;
            const ulonglong2* pa = (const ulonglong2*)&sA[buf][k * 64 + ty * 8];
            ulonglong2 a01 = pa[0];
            ulonglong2 a23 = pa[1];
            unsigned long long ap[4] = { a01.x, a01.y, a23.x, a23.y };
            const ulonglong2* pr = (const ulonglong2*)&sRd[buf][k * RDW + rdOff];
            ulonglong2 r01 = pr[0];
            ulonglong2 r23 = pr[1];
            unsigned long long rp[4] = { r01.x, r01.y, r23.x, r23.y };
#pragma unroll
            for (int vp = 0; vp < 4; vp++)
#pragma unroll
                for (int jj = 0; jj < 4; jj++)
                    acc[vp][jj] = fma2(ap[vp], rp[jj], acc[vp][jj]);
        }

        // ---------- Phase A for next tile into the other buffer ----------
        const int nxt = tile + NC;
        if (nxt < NTILES) phaseA(nxt, buf ^ 1);
        __syncthreads();
        buf ^= 1;
    }

    // ---------- Reduce 2 k-groups into Ms (sA[0]+sA[1] = 4096 = 64x64) -----
    float* Ms = sA[0];
    if (grp == 0) {
#pragma unroll
        for (int vp = 0; vp < 4; vp++)
#pragma unroll
            for (int jj = 0; jj < 4; jj++) {
                unsigned int lo, hi;
                asm("mov.b64 {%0,%1}, %2;" : "=r"(lo), "=r"(hi) : "l"(acc[vp][jj]));
                const int v = ty * 8 + vp * 2;
                const int j = tx * 4 + jj;
                Ms[v * 64 + j]       = __uint_as_float(lo);
                Ms[(v + 1) * 64 + j] = __uint_as_float(hi);
            }
    }
    __syncthreads();
    if (grp == 1) {
#pragma unroll
        for (int vp = 0; vp < 4; vp++)
#pragma unroll
            for (int jj = 0; jj < 4; jj++) {
                unsigned int lo, hi;
                asm("mov.b64 {%0,%1}, %2;" : "=r"(lo), "=r"(hi) : "l"(acc[vp][jj]));
                const int v = ty * 8 + vp * 2;
                const int j = tx * 4 + jj;
                Ms[v * 64 + j]       += __uint_as_float(lo);
                Ms[(v + 1) * 64 + j] += __uint_as_float(hi);
            }
    }
    __syncthreads();

    // ---------- Store transposed slab: part[blk][j*60+v] = Ms[v][j] ----------
    float* dst = g_part + (size_t)blockIdx.x * 3600;
    for (int e = tid; e < 3600; e += 256) {
        const int j = e / 60;
        const int v = e - j * 60;
        dst[e] = Ms[v * 64 + j];
    }
}

// ============================================================================
// Kernel 2a: wide vectorized slab reduction, 296 -> 8 per column.
// grid (60 j, 8 s) x 128 threads; thread (v4, l) sums slabs c = s + 8l + 64m
// as independent LDG.128 (4-5 per thread; thousands of lines in flight).
// Output: g_red[(j*60+v)*8 + s].
// ============================================================================
__global__ __launch_bounds__(128)
void k2a_reduce() {
    const int j  = blockIdx.x;
    const int s  = blockIdx.y;
    const int t  = threadIdx.x;
    const int v4 = t >> 3;   // 0..15 (15 inactive)
    const int l  = t & 7;    // 0..7

    __shared__ float4 sred[15][8];

    float4 acc = make_float4(0.f, 0.f, 0.f, 0.f);
    if (v4 < 15) {
        const float* base = g_part + j * 60 + v4 * 4;
#pragma unroll
        for (int m = 0; m < 5; m++) {
            const int idx = l + 8 * m;           // 0..39
            if (idx < 37) {
                const int c = s + 8 * idx;       // < 296
                float4 vv = *(const float4*)(base + (size_t)c * 3600);
                acc.x += vv.x; acc.y += vv.y; acc.z += vv.z; acc.w += vv.w;
            }
        }
        sred[v4][l] = acc;
    }
    __syncthreads();

    if (t < 60) {
        const int v = t;
        const int q = v >> 2, comp = v & 3;
        float sum = 0.f;
#pragma unroll
        for (int l2 = 0; l2 < 8; l2++) {
            float4 vv = sred[q][l2];
            sum += (comp == 0) ? vv.x : (comp == 1) ? vv.y
                 : (comp == 2) ? vv.z : vv.w;
        }
        g_red[(j * 60 + v) * 8 + s] = sum;
    }
}

// ============================================================================
// Kernel 2b: one CTA per column j, 64 threads. Sums 8 s-partials per (j,v)
// (2 float4 loads, 115 KB total = L2-hot), then the tiny epilogue.
// ============================================================================
__global__ __launch_bounds__(64)
void k2b_epilogue(const float* __restrict__ W2,
                  const float* __restrict__ b_s,
                  const float* __restrict__ V_s,
                  float* __restrict__ out) {
    const int j   = blockIdx.x;
    const int tid = threadIdx.x;

    __shared__ float Mcol[64];
    __shared__ float sig[64];
    __shared__ float sS[64];

    float s = 0.f;
    if (tid < 60) {
        const float4* p = (const float4*)(g_red + (j * 60 + tid) * 8);
        float4 p0 = p[0], p1 = p[1];
        s = ((p0.x + p0.y) + (p0.z + p0.w)) + ((p1.x + p1.y) + (p1.z + p1.w));
    }
    Mcol[tid] = s;
    __syncthreads();

    float sg = 0.f;
    if (tid < 60) {
        const int k = tid;
        float pr = 0.f;
#pragma unroll 4
        for (int vv = 0; vv < 60; vv++) pr = fmaf(W2[vv * 60 + k], Mcol[vv], pr);
        pr += b_s[k * 60 + j];
        sg = 1.f / (1.f + expf(-pr));
    }
    sig[tid] = sg;
    __syncthreads();

    float Si = 0.f;
    if (tid < 60) {
        const float4* vr = (const float4*)(V_s + tid * 60);
#pragma unroll
        for (int q = 0; q < 15; q++) {
            float4 vx = vr[q];
            Si = fmaf(vx.x, sig[q * 4 + 0], Si);
            Si = fmaf(vx.y, sig[q * 4 + 1], Si);
            Si = fmaf(vx.z, sig[q * 4 + 2], Si);
            Si = fmaf(vx.w, sig[q * 4 + 3], Si);
        }
    }
    sS[tid] = (tid < 60) ? Si : -1e30f;
    __syncthreads();

    if (tid < 60) {
        float m = -1e30f;
#pragma unroll 4
        for (int i2 = 0; i2 < 60; i2++) m = fmaxf(m, sS[i2]);
        float sum = 0.f;
#pragma unroll 4
        for (int i2 = 0; i2 < 60; i2++) sum += expf(sS[i2] - m);
        out[tid * 60 + j] = expf(Si - m) / sum;
    }
}

// ============================================================================
extern "C" void kernel_launch(void* const* d_in, const int* in_sizes, int n_in,
                              void* d_out, int out_size) {
    const float* x   = (const float*)d_in[0];
    const float* W1  = (const float*)d_in[1];
    const float* W2  = (const float*)d_in[2];
    const float* W3  = (const float*)d_in[3];
    const float* b_s = (const float*)d_in[4];
    const float* V_s = (const float*)d_in[5];
    float* out = (float*)d_out;

    const int smem_bytes = (2 * KB * 64 + 2 * KB * RDW) * 4;  // 52224 B
    cudaFuncSetAttribute(k1_gram, cudaFuncAttributeMaxDynamicSharedMemorySize,
                         smem_bytes);

    k1_gram<<<NC, 256, smem_bytes>>>(x, W1, W3);
    k2a_reduce<<<dim3(60, 8), 128>>>();
    k2b_epilogue<<<V_DIM, 64>>>(W2, b_s, V_s, out);
}

// round 13
// speedup vs baseline: 1.4089x; 1.4089x over previous
#include <cuda_runtime.h>
#include <cstdint>
#include <cstddef>

// Problem constants
#define B_TOT  131072
#define T_DIM  5
#define V_DIM  60
#define TV     300
#define KB     32                 // b-rows per k-tile
#define NC     296                // CTAs in kernel 1
#define NTILES (B_TOT / KB)       // 4096

// Single cross-CTA accumulator: g_red[j*60+v] = M[v][j] (atomic-summed)
__device__ float g_red[3600];

// Packed f32x2 FMA (sm_100+); scalar fallback otherwise. Same numerics (.rn).
__device__ __forceinline__ unsigned long long fma2(unsigned long long a,
                                                   unsigned long long b,
                                                   unsigned long long c) {
#if defined(__CUDA_ARCH__) && (__CUDA_ARCH__ >= 1000)
    unsigned long long d;
    asm("fma.rn.f32x2 %0, %1, %2, %3;" : "=l"(d) : "l"(a), "l"(b), "l"(c));
    return d;
#else
    float2 fa = *reinterpret_cast<float2*>(&a);
    float2 fb = *reinterpret_cast<float2*>(&b);
    float2 fc = *reinterpret_cast<float2*>(&c);
    float2 fd;
    fd.x = fmaf(fa.x, fb.x, fc.x);
    fd.y = fmaf(fa.y, fb.y, fc.y);
    return *reinterpret_cast<unsigned long long*>(&fd);
#endif
}

// {f, f} packed into a 64-bit register pair
__device__ __forceinline__ unsigned long long dup2(float f) {
    unsigned long long r;
    asm("mov.b64 %0, {%1, %2};" : "=l"(r) : "f"(f), "f"(f));
    return r;
}

// ============================================================================
// Kernel 0: zero the accumulator (must precede k1's atomics; same stream).
// ============================================================================
__global__ __launch_bounds__(240)
void k0_zero() {
    const int e = blockIdx.x * 240 + threadIdx.x;
    if (e < 3600) g_red[e] = 0.f;
}

// ============================================================================
// Kernel 1 (exact R11 GEMM config — measured 44.5us): thread tile 8v x 4j,
// f32x2 pairs along v; static smem 33.4 KB -> 3 CTAs/SM; KB=32 double-buffered,
// one barrier per tile. Epilogue: atomicAdd the 60x60 partial into g_red
// (spread addresses, hidden under other CTAs' compute) — NO slab readback.
// ============================================================================
__global__ __launch_bounds__(256, 3)
void k1_gram(const float* __restrict__ x,
             const float* __restrict__ W1,
             const float* __restrict__ W3) {
    __shared__ float sA[2][KB * 64];   // plain a  (16 KB total)
    __shared__ float sR[2][KB * 68];   // plain r, 68-float rows (17.4 KB)

    const int tid = threadIdx.x;

    float w1[T_DIM], w3[T_DIM];
#pragma unroll
    for (int t = 0; t < T_DIM; t++) { w1[t] = W1[t]; w3[t] = W3[t]; }

    // Phase-B mapping: 2 k-groups x (8 ty x 16 tx); tile 8v x 4j per thread
    const int grp = tid >> 7;        // 0..1 : handles k = grp + 2*kk
    const int gt  = tid & 127;
    const int ty  = gt >> 4;         // 0..7 : v = ty*8 + 2*vp + {0,1}
    const int tx  = gt & 15;         // 0..15: j = tx*4 + jj

    // Phase-A mapping: 16 b-rows x 16 v-lanes (lane 15 = zero pad), 2 passes
    const int rowA  = tid >> 4;      // 0..15
    const int laneA = tid & 15;      // 0..15

    unsigned long long acc[4][4];    // [vp][jj] -> 32 registers
#pragma unroll
    for (int vp = 0; vp < 4; vp++)
#pragma unroll
        for (int jj = 0; jj < 4; jj++) acc[vp][jj] = 0ull;

    auto phaseA = [&](int tile, int buf) {
#pragma unroll
        for (int p = 0; p < 2; p++) {
            const int k = rowA + 16 * p;             // 0..31
            float4 a4 = make_float4(0.f, 0.f, 0.f, 0.f);
            float4 r4 = make_float4(0.f, 0.f, 0.f, 0.f);
            if (laneA < 15) {
                const float* xb = x + (size_t)(tile * KB + k) * TV + laneA * 4;
#pragma unroll
                for (int t = 0; t < T_DIM; t++) {
                    float4 xv = *(const float4*)(xb + t * V_DIM);
                    a4.x = fmaf(xv.x, w1[t], a4.x); r4.x = fmaf(xv.x, w3[t], r4.x);
                    a4.y = fmaf(xv.y, w1[t], a4.y); r4.y = fmaf(xv.y, w3[t], r4.y);
                    a4.z = fmaf(xv.z, w1[t], a4.z); r4.z = fmaf(xv.z, w3[t], r4.z);
                    a4.w = fmaf(xv.w, w1[t], a4.w); r4.w = fmaf(xv.w, w3[t], r4.w);
                }
            }
            *(float4*)&sA[buf][k * 64 + laneA * 4] = a4;
            *(float4*)&sR[buf][k * 68 + laneA * 4] = r4;
        }
    };

    // Prologue
    phaseA(blockIdx.x, 0);
    __syncthreads();

    int buf = 0;
    for (int tile = blockIdx.x; tile < NTILES; tile += NC) {
        // ---------- Phase B on buf: 16 kk x 16 fma2 ----------
#pragma unroll
        for (int kk = 0; kk < KB / 2; kk++) {
            const int k = grp + kk * 2;
            const ulonglong2* pa = (const ulonglong2*)&sA[buf][k * 64 + ty * 8];
            ulonglong2 a01 = pa[0];              // natural {a,a+1} pairs
            ulonglong2 a23 = pa[1];
            unsigned long long ap[4] = { a01.x, a01.y, a23.x, a23.y };
            float4 r4 = *(const float4*)&sR[buf][k * 68 + tx * 4];
            unsigned long long rp[4] = { dup2(r4.x), dup2(r4.y),
                                         dup2(r4.z), dup2(r4.w) };
#pragma unroll
            for (int vp = 0; vp < 4; vp++)
#pragma unroll
                for (int jj = 0; jj < 4; jj++)
                    acc[vp][jj] = fma2(ap[vp], rp[jj], acc[vp][jj]);
        }

        // ---------- Phase A for next tile into the other buffer ----------
        const int nxt = tile + NC;
        if (nxt < NTILES) phaseA(nxt, buf ^ 1);
        __syncthreads();
        buf ^= 1;
    }

    // ---------- Reduce the 2 k-groups into Ms (sA contiguous: 64x64) -------
    float* Ms = &sA[0][0];
    if (grp == 0) {
#pragma unroll
        for (int vp = 0; vp < 4; vp++)
#pragma unroll
            for (int jj = 0; jj < 4; jj++) {
                unsigned int lo, hi;
                asm("mov.b64 {%0,%1}, %2;" : "=r"(lo), "=r"(hi) : "l"(acc[vp][jj]));
                const int v = ty * 8 + vp * 2;
                const int j = tx * 4 + jj;
                Ms[v * 64 + j]       = __uint_as_float(lo);
                Ms[(v + 1) * 64 + j] = __uint_as_float(hi);
            }
    }
    __syncthreads();
    if (grp == 1) {
#pragma unroll
        for (int vp = 0; vp < 4; vp++)
#pragma unroll
            for (int jj = 0; jj < 4; jj++) {
                unsigned int lo, hi;
                asm("mov.b64 {%0,%1}, %2;" : "=r"(lo), "=r"(hi) : "l"(acc[vp][jj]));
                const int v = ty * 8 + vp * 2;
                const int j = tx * 4 + jj;
                Ms[v * 64 + j]       += __uint_as_float(lo);
                Ms[(v + 1) * 64 + j] += __uint_as_float(hi);
            }
    }
    __syncthreads();

    // ---------- Atomic epilogue: g_red[j*60+v] += Ms[v][j] ------------------
    for (int e = tid; e < 3600; e += 256) {
        const int j = e / 60;
        const int v = e - j * 60;
        atomicAdd(&g_red[e], Ms[v * 64 + j]);
    }
}

// ============================================================================
// Kernel 2: one CTA per output column j, 64 threads. Mcol comes straight
// from g_red (14.4 KB, L2-hot). Tiny epilogue unchanged.
// ============================================================================
__global__ __launch_bounds__(64)
void k2_epilogue(const float* __restrict__ W2,
                 const float* __restrict__ b_s,
                 const float* __restrict__ V_s,
                 float* __restrict__ out) {
    const int j   = blockIdx.x;
    const int tid = threadIdx.x;

    __shared__ float Mcol[64];
    __shared__ float sig[64];
    __shared__ float sS[64];

    Mcol[tid] = (tid < 60) ? g_red[j * 60 + tid] : 0.f;
    __syncthreads();

    float sg = 0.f;
    if (tid < 60) {
        const int k = tid;
        float pr = 0.f;
#pragma unroll 4
        for (int vv = 0; vv < 60; vv++) pr = fmaf(W2[vv * 60 + k], Mcol[vv], pr);
        pr += b_s[k * 60 + j];
        sg = 1.f / (1.f + expf(-pr));
    }
    sig[tid] = sg;
    __syncthreads();

    float Si = 0.f;
    if (tid < 60) {
        const float4* vr = (const float4*)(V_s + tid * 60);  // 240B rows, aligned
#pragma unroll
        for (int q = 0; q < 15; q++) {
            float4 vx = vr[q];
            Si = fmaf(vx.x, sig[q * 4 + 0], Si);
            Si = fmaf(vx.y, sig[q * 4 + 1], Si);
            Si = fmaf(vx.z, sig[q * 4 + 2], Si);
            Si = fmaf(vx.w, sig[q * 4 + 3], Si);
        }
    }
    sS[tid] = (tid < 60) ? Si : -1e30f;
    __syncthreads();

    if (tid < 60) {
        float m = -1e30f;
#pragma unroll 4
        for (int i2 = 0; i2 < 60; i2++) m = fmaxf(m, sS[i2]);
        float sum = 0.f;
#pragma unroll 4
        for (int i2 = 0; i2 < 60; i2++) sum += expf(sS[i2] - m);
        out[tid * 60 + j] = expf(Si - m) / sum;
    }
}

// ============================================================================
extern "C" void kernel_launch(void* const* d_in, const int* in_sizes, int n_in,
                              void* d_out, int out_size) {
    const float* x   = (const float*)d_in[0];
    const float* W1  = (const float*)d_in[1];
    const float* W2  = (const float*)d_in[2];
    const float* W3  = (const float*)d_in[3];
    const float* b_s = (const float*)d_in[4];
    const float* V_s = (const float*)d_in[5];
    float* out = (float*)d_out;

    k0_zero<<<15, 240>>>();
    k1_gram<<<NC, 256>>>(x, W1, W3);
    k2_epilogue<<<V_DIM, 64>>>(W2, b_s, V_s, out);
}